// round 5
// baseline (speedup 1.0000x reference)
#include <cuda_runtime.h>
#include <math.h>

#define NB       16
#define NPTS     4096
#define C        8                        // candidates per thread (register-resident)
#define THREADS  128
#define CANDS_PER_BLOCK (THREADS * C)     // 1024
#define CCHUNKS  (NPTS / CANDS_PER_BLOCK) // 4
#define ROWSPLIT 32
#define ROWS_PER_BLOCK (NPTS / ROWSPLIT)  // 128
#define RPAIRS   (ROWS_PER_BLOCK / 2)     // 64
#define EPS      1e-6f
#define TOTAL_Q  (NB * NPTS)

// Scratch (no cudaMalloc allowed)
// g_rowpair: per row pair (i0=2k, i1=2k+1), two float4s:
//   [2k+0] = (x_i0, x_i1, y_i0, y_i1)
//   [2k+1] = (z_i0, z_i1, w_i0, w_i1)   w = ||y_i||^2
__device__ float4   g_rowpair[NB * NPTS];
__device__ float4   g_col[NB * NPTS];          // (-2x, -2y, -2z, ||x||^2)
__device__ unsigned g_rowmin[NB * NPTS];
__device__ unsigned g_colmin[NB * NPTS];

// Order-preserving float->uint (all floats incl. negatives)
__device__ __forceinline__ unsigned flipf(float f) {
    unsigned b = __float_as_uint(f);
    return b ^ (0x80000000u | (unsigned)((int)b >> 31));
}
__device__ __forceinline__ float unflipf(unsigned u) {
    unsigned b = (u & 0x80000000u) ? (u ^ 0x80000000u) : ~u;
    return __uint_as_float(b);
}

__device__ __forceinline__ unsigned long long pack2(float a, float b) {
    unsigned long long r;
    asm("mov.b64 %0, {%1, %2};" : "=l"(r) : "f"(a), "f"(b));
    return r;
}

// Warp-collective min reduction, single instruction (sm_80+)
__device__ __forceinline__ unsigned redux_min_u32(unsigned v) {
    unsigned r;
    asm("redux.sync.min.u32 %0, %1, 0xFFFFFFFF;" : "=r"(r) : "r"(v));
    return r;
}

// ---------------------------------------------------------------------------
// Pack kernel: one thread per row PAIR.
// ---------------------------------------------------------------------------
__global__ void pack_kernel(const float* __restrict__ x,
                            const float* __restrict__ y,
                            float* __restrict__ out) {
    int k = blockIdx.x * blockDim.x + threadIdx.x;   // pair index
    if (k == 0) out[0] = 0.0f;
    if (k >= NB * NPTS / 2) return;

    int i0 = 2 * k, i1 = 2 * k + 1;

    {
        const float* p0 = y + (size_t)i0 * 3;
        const float* p1 = y + (size_t)i1 * 3;
        float x0 = p0[0], y0 = p0[1], z0 = p0[2];
        float x1 = p1[0], y1 = p1[1], z1 = p1[2];
        float w0 = x0 * x0 + y0 * y0 + z0 * z0;
        float w1 = x1 * x1 + y1 * y1 + z1 * z1;
        g_rowpair[2 * k + 0] = make_float4(x0, x1, y0, y1);
        g_rowpair[2 * k + 1] = make_float4(z0, z1, w0, w1);
    }
    {
        const float* p0 = x + (size_t)i0 * 3;
        const float* p1 = x + (size_t)i1 * 3;
        float a = p0[0], b = p0[1], c = p0[2];
        g_col[i0] = make_float4(-2.f * a, -2.f * b, -2.f * c, a * a + b * b + c * c);
        float u = p1[0], v = p1[1], w = p1[2];
        g_col[i1] = make_float4(-2.f * u, -2.f * v, -2.f * w, u * u + v * v + w * w);
    }
    g_rowmin[i0] = 0xFFFFFFFFu; g_rowmin[i1] = 0xFFFFFFFFu;
    g_colmin[i0] = 0xFFFFFFFFu; g_colmin[i1] = 0xFFFFFFFFu;
}

// ---------------------------------------------------------------------------
// Fused pass: grid (CCHUNKS, ROWSPLIT, NB) = (4, 32, 16) = 2048 blocks.
// Per warp-iter (512 pair-evals): 32 FFMA2/FADD2 + 30 FMNMX + 2 REDUX.
// Rowmin reduction: per-thread tree -> flipped-uint -> redux.sync.min -> RED.
// ---------------------------------------------------------------------------
__global__ __launch_bounds__(THREADS, 4)
void chamfer_fused_kernel() {
    __shared__ float4 rowtile[RPAIRS * 2];   // 2 KB

    const int b  = blockIdx.z;
    const int rs = blockIdx.y;
    const int cc = blockIdx.x;

    const int row0 = rs * ROWS_PER_BLOCK;
    const int j0   = cc * CANDS_PER_BLOCK + threadIdx.x * C;

    const float4* __restrict__ RPbase = g_rowpair + (size_t)b * NPTS + row0;
    const float4* __restrict__ Cd     = g_col     + (size_t)b * NPTS + j0;

    // Load candidates, duplicate into packed 64-bit registers
    unsigned long long cxd[C], cyd[C], czd[C], cwd[C];
    float cm0[C], cm1[C];
#pragma unroll
    for (int c = 0; c < C; c++) {
        float4 f = Cd[c];
        cxd[c] = pack2(f.x, f.x);
        cyd[c] = pack2(f.y, f.y);
        czd[c] = pack2(f.z, f.z);
        cwd[c] = pack2(f.w, f.w);
        cm0[c] = 3.4e38f;
        cm1[c] = 3.4e38f;
    }

    // Stage row slice
    for (int i = threadIdx.x; i < RPAIRS * 2; i += THREADS)
        rowtile[i] = RPbase[i];
    __syncthreads();

    const int lane = threadIdx.x & 31;
    const ulonglong2* tp = (const ulonglong2*)rowtile;

#pragma unroll 2
    for (int rp = 0; rp < RPAIRS; rp++) {
        ulonglong2 e0 = tp[2 * rp + 0];   // .x = xpair, .y = ypair
        ulonglong2 e1 = tp[2 * rp + 1];   // .x = zpair, .y = wpair (y2)

        float v0s[C], v1s[C];
#pragma unroll
        for (int c = 0; c < C; c++) {
            unsigned long long t;
            asm("fma.rn.f32x2 %0, %1, %2, %3;" : "=l"(t) : "l"(e1.x), "l"(czd[c]), "l"(cwd[c]));
            asm("fma.rn.f32x2 %0, %1, %2, %0;" : "+l"(t) : "l"(e0.y), "l"(cyd[c]));
            asm("fma.rn.f32x2 %0, %1, %2, %0;" : "+l"(t) : "l"(e0.x), "l"(cxd[c]));
            asm("add.rn.f32x2 %0, %0, %1;"     : "+l"(t) : "l"(e1.y));
            float v0, v1;
            asm("mov.b64 {%0, %1}, %2;" : "=f"(v0), "=f"(v1) : "l"(t));
            v0s[c] = v0; v1s[c] = v1;
            cm0[c] = fminf(cm0[c], v0);          // colmin, independent chains
            cm1[c] = fminf(cm1[c], v1);
        }

        // Row-min trees over C candidates (each row separately)
#pragma unroll
        for (int st = 1; st < C; st <<= 1)
#pragma unroll
            for (int k = 0; k < C; k += 2 * st) {
                v0s[k] = fminf(v0s[k], v0s[k + st]);
                v1s[k] = fminf(v1s[k], v1s[k + st]);
            }

        // Warp reduction: flipped-uint + redux.sync.min (replaces shfl butterfly)
        unsigned f0 = redux_min_u32(flipf(v0s[0]));
        unsigned f1 = redux_min_u32(flipf(v1s[0]));
        if (lane == 0) {
            atomicMin(&g_rowmin[b * NPTS + row0 + 2 * rp + 0], f0);
            atomicMin(&g_rowmin[b * NPTS + row0 + 2 * rp + 1], f1);
        }
    }

    // Flush colmin partials
#pragma unroll
    for (int c = 0; c < C; c++)
        atomicMin(&g_colmin[b * NPTS + j0 + c], flipf(fminf(cm0[c], cm1[c])));
}

// ---------------------------------------------------------------------------
__global__ void finalize_kernel(float* __restrict__ out) {
    int idx = blockIdx.x * blockDim.x + threadIdx.x;

    float local = 0.0f;
    if (idx < NB * NPTS) {
        float vr = unflipf(g_rowmin[idx]);
        float vc = unflipf(g_colmin[idx]);
        local  = sqrtf(EPS + fmaxf(vr, 0.0f));
        local += sqrtf(EPS + fmaxf(vc, 0.0f));
    }

#pragma unroll
    for (int o = 16; o > 0; o >>= 1)
        local += __shfl_down_sync(0xFFFFFFFFu, local, o);

    __shared__ float warp_sums[8];
    int lane = threadIdx.x & 31;
    int wid  = threadIdx.x >> 5;
    if (lane == 0) warp_sums[wid] = local;
    __syncthreads();
    if (wid == 0) {
        float sv = (lane < (int)(blockDim.x >> 5)) ? warp_sums[lane] : 0.0f;
#pragma unroll
        for (int o = 4; o > 0; o >>= 1)
            sv += __shfl_down_sync(0xFFFFFFFFu, sv, o);
        if (lane == 0) atomicAdd(out, sv * (1.0f / (float)TOTAL_Q));
    }
}

extern "C" void kernel_launch(void* const* d_in, const int* in_sizes, int n_in,
                              void* d_out, int out_size) {
    const float* x = (const float*)d_in[0];
    const float* y = (const float*)d_in[1];
    float* out = (float*)d_out;

    pack_kernel<<<(NB * NPTS / 2 + 255) / 256, 256>>>(x, y, out);

    dim3 grid(CCHUNKS, ROWSPLIT, NB);   // (4, 32, 16) = 2048 blocks
    chamfer_fused_kernel<<<grid, THREADS>>>();

    finalize_kernel<<<(NB * NPTS + 255) / 256, 256>>>(out);
}

// round 6
// speedup vs baseline: 1.3746x; 1.3746x over previous
#include <cuda_runtime.h>
#include <math.h>

#define NB       16
#define NPTS     4096
#define C        8                        // candidates per thread (register-resident)
#define THREADS  128
#define CANDS_PER_BLOCK (THREADS * C)     // 1024
#define CCHUNKS  (NPTS / CANDS_PER_BLOCK) // 4
#define ROWSPLIT 32
#define ROWS_PER_BLOCK (NPTS / ROWSPLIT)  // 128
#define RPAIRS   (ROWS_PER_BLOCK / 2)     // 64
#define EPS      1e-6f
#define TOTAL_Q  (NB * NPTS)

// Scratch (no cudaMalloc allowed)
// g_rowpair: per row pair (i0=2k, i1=2k+1), two float4s:
//   [2k+0] = (x_i0, x_i1, y_i0, y_i1)
//   [2k+1] = (z_i0, z_i1, w_i0, w_i1)   w = ||y_i||^2
__device__ float4   g_rowpair[NB * NPTS];
__device__ float4   g_col[NB * NPTS];          // (-2x, -2y, -2z, ||x||^2)
__device__ unsigned g_rowmin[NB * NPTS];
__device__ unsigned g_colmin[NB * NPTS];

// Order-preserving float->uint (all floats incl. negatives)
__device__ __forceinline__ unsigned flipf(float f) {
    unsigned b = __float_as_uint(f);
    return b ^ (0x80000000u | (unsigned)((int)b >> 31));
}
__device__ __forceinline__ float unflipf(unsigned u) {
    unsigned b = (u & 0x80000000u) ? (u ^ 0x80000000u) : ~u;
    return __uint_as_float(b);
}

__device__ __forceinline__ unsigned long long pack2(float a, float b) {
    unsigned long long r;
    asm("mov.b64 %0, {%1, %2};" : "=l"(r) : "f"(a), "f"(b));
    return r;
}

// 3-input min (PTX ISA 8.0, sm_90+) -> single fixed-lat alu op
__device__ __forceinline__ float fmin3(float a, float b, float c) {
    float r;
    asm("min.f32 %0, %1, %2, %3;" : "=f"(r) : "f"(a), "f"(b), "f"(c));
    return r;
}

// ---------------------------------------------------------------------------
// Pack kernel: one thread per row PAIR.
// ---------------------------------------------------------------------------
__global__ void pack_kernel(const float* __restrict__ x,
                            const float* __restrict__ y,
                            float* __restrict__ out) {
    int k = blockIdx.x * blockDim.x + threadIdx.x;   // pair index
    if (k == 0) out[0] = 0.0f;
    if (k >= NB * NPTS / 2) return;

    int i0 = 2 * k, i1 = 2 * k + 1;

    {
        const float* p0 = y + (size_t)i0 * 3;
        const float* p1 = y + (size_t)i1 * 3;
        float x0 = p0[0], y0 = p0[1], z0 = p0[2];
        float x1 = p1[0], y1 = p1[1], z1 = p1[2];
        float w0 = x0 * x0 + y0 * y0 + z0 * z0;
        float w1 = x1 * x1 + y1 * y1 + z1 * z1;
        g_rowpair[2 * k + 0] = make_float4(x0, x1, y0, y1);
        g_rowpair[2 * k + 1] = make_float4(z0, z1, w0, w1);
    }
    {
        const float* p0 = x + (size_t)i0 * 3;
        const float* p1 = x + (size_t)i1 * 3;
        float a = p0[0], b = p0[1], c = p0[2];
        g_col[i0] = make_float4(-2.f * a, -2.f * b, -2.f * c, a * a + b * b + c * c);
        float u = p1[0], v = p1[1], w = p1[2];
        g_col[i1] = make_float4(-2.f * u, -2.f * v, -2.f * w, u * u + v * v + w * w);
    }
    g_rowmin[i0] = 0xFFFFFFFFu; g_rowmin[i1] = 0xFFFFFFFFu;
    g_colmin[i0] = 0xFFFFFFFFu; g_colmin[i1] = 0xFFFFFFFFu;
}

// ---------------------------------------------------------------------------
// Fused pass: grid (CCHUNKS, ROWSPLIT, NB) = (4, 32, 16) = 2048 blocks.
// Per warp-iter (512 pair-evals): 32 FFMA2/FADD2 (fma) + 8 min3 (colmin)
// + 8 min3/min (row trees) + 10 SHFL + 10 FMNMX (butterfly).
// ---------------------------------------------------------------------------
__global__ __launch_bounds__(THREADS, 4)
void chamfer_fused_kernel() {
    __shared__ float4 rowtile[RPAIRS * 2];   // 2 KB

    const int b  = blockIdx.z;
    const int rs = blockIdx.y;
    const int cc = blockIdx.x;

    const int row0 = rs * ROWS_PER_BLOCK;
    const int j0   = cc * CANDS_PER_BLOCK + threadIdx.x * C;

    const float4* __restrict__ RPbase = g_rowpair + (size_t)b * NPTS + row0;
    const float4* __restrict__ Cd     = g_col     + (size_t)b * NPTS + j0;

    // Load candidates, duplicate into packed 64-bit registers
    unsigned long long cxd[C], cyd[C], czd[C], cwd[C];
    float cm[C];
#pragma unroll
    for (int c = 0; c < C; c++) {
        float4 f = Cd[c];
        cxd[c] = pack2(f.x, f.x);
        cyd[c] = pack2(f.y, f.y);
        czd[c] = pack2(f.z, f.z);
        cwd[c] = pack2(f.w, f.w);
        cm[c]  = 3.4e38f;
    }

    // Stage row slice
    for (int i = threadIdx.x; i < RPAIRS * 2; i += THREADS)
        rowtile[i] = RPbase[i];
    __syncthreads();

    const int lane = threadIdx.x & 31;
    const ulonglong2* tp = (const ulonglong2*)rowtile;

#pragma unroll 2
    for (int rp = 0; rp < RPAIRS; rp++) {
        ulonglong2 e0 = tp[2 * rp + 0];   // .x = xpair, .y = ypair
        ulonglong2 e1 = tp[2 * rp + 1];   // .x = zpair, .y = wpair (y2)

        float v0s[C], v1s[C];
#pragma unroll
        for (int c = 0; c < C; c++) {
            unsigned long long t;
            asm("fma.rn.f32x2 %0, %1, %2, %3;" : "=l"(t) : "l"(e1.x), "l"(czd[c]), "l"(cwd[c]));
            asm("fma.rn.f32x2 %0, %1, %2, %0;" : "+l"(t) : "l"(e0.y), "l"(cyd[c]));
            asm("fma.rn.f32x2 %0, %1, %2, %0;" : "+l"(t) : "l"(e0.x), "l"(cxd[c]));
            asm("add.rn.f32x2 %0, %0, %1;"     : "+l"(t) : "l"(e1.y));
            float v0, v1;
            asm("mov.b64 {%0, %1}, %2;" : "=f"(v0), "=f"(v1) : "l"(t));
            v0s[c] = v0; v1s[c] = v1;
            cm[c] = fmin3(cm[c], v0, v1);        // colmin merge, single min3
        }

        // Row-min trees over 8 candidates: 4 ops each via min3
        float r0 = fmin3(fmin3(v0s[0], v0s[1], v0s[2]),
                         fmin3(v0s[3], v0s[4], v0s[5]),
                         fminf(v0s[6], v0s[7]));
        float r1 = fmin3(fmin3(v1s[0], v1s[1], v1s[2]),
                         fmin3(v1s[3], v1s[4], v1s[5]),
                         fminf(v1s[6], v1s[7]));

        // Warp butterflies (pipelinable; REDUX regressed in R5)
#pragma unroll
        for (int o = 16; o > 0; o >>= 1) {
            r0 = fminf(r0, __shfl_xor_sync(0xFFFFFFFFu, r0, o));
            r1 = fminf(r1, __shfl_xor_sync(0xFFFFFFFFu, r1, o));
        }
        if (lane == 0) {
            atomicMin(&g_rowmin[b * NPTS + row0 + 2 * rp + 0], flipf(r0));
            atomicMin(&g_rowmin[b * NPTS + row0 + 2 * rp + 1], flipf(r1));
        }
    }

    // Flush colmin partials
#pragma unroll
    for (int c = 0; c < C; c++)
        atomicMin(&g_colmin[b * NPTS + j0 + c], flipf(cm[c]));
}

// ---------------------------------------------------------------------------
__global__ void finalize_kernel(float* __restrict__ out) {
    int idx = blockIdx.x * blockDim.x + threadIdx.x;

    float local = 0.0f;
    if (idx < NB * NPTS) {
        float vr = unflipf(g_rowmin[idx]);
        float vc = unflipf(g_colmin[idx]);
        local  = sqrtf(EPS + fmaxf(vr, 0.0f));
        local += sqrtf(EPS + fmaxf(vc, 0.0f));
    }

#pragma unroll
    for (int o = 16; o > 0; o >>= 1)
        local += __shfl_down_sync(0xFFFFFFFFu, local, o);

    __shared__ float warp_sums[8];
    int lane = threadIdx.x & 31;
    int wid  = threadIdx.x >> 5;
    if (lane == 0) warp_sums[wid] = local;
    __syncthreads();
    if (wid == 0) {
        float sv = (lane < (int)(blockDim.x >> 5)) ? warp_sums[lane] : 0.0f;
#pragma unroll
        for (int o = 4; o > 0; o >>= 1)
            sv += __shfl_down_sync(0xFFFFFFFFu, sv, o);
        if (lane == 0) atomicAdd(out, sv * (1.0f / (float)TOTAL_Q));
    }
}

extern "C" void kernel_launch(void* const* d_in, const int* in_sizes, int n_in,
                              void* d_out, int out_size) {
    const float* x = (const float*)d_in[0];
    const float* y = (const float*)d_in[1];
    float* out = (float*)d_out;

    pack_kernel<<<(NB * NPTS / 2 + 255) / 256, 256>>>(x, y, out);

    dim3 grid(CCHUNKS, ROWSPLIT, NB);   // (4, 32, 16) = 2048 blocks
    chamfer_fused_kernel<<<grid, THREADS>>>();

    finalize_kernel<<<(NB * NPTS + 255) / 256, 256>>>(out);
}

// round 8
// speedup vs baseline: 1.8347x; 1.3347x over previous
#include <cuda_runtime.h>
#include <math.h>

#define NB       16
#define NPTS     4096
#define C        8                        // candidates per thread (register-resident)
#define THREADS  128
#define WARPS    (THREADS / 32)
#define CANDS_PER_BLOCK (THREADS * C)     // 1024
#define CCHUNKS  (NPTS / CANDS_PER_BLOCK) // 4
#define ROWSPLIT 32
#define ROWS_PER_BLOCK (NPTS / ROWSPLIT)  // 128
#define RPAIRS   (ROWS_PER_BLOCK / 2)     // 64
#define GROUPS   8                        // 8 row-pairs (16 rows) per transpose batch
#define TPG      (RPAIRS / GROUPS)        // 8 iters per group
#define EPS      1e-6f
#define TOTAL_Q  (NB * NPTS)

// Scratch (no cudaMalloc allowed)
__device__ float4   g_rowpair[NB * NPTS];      // pair 2k:(x0,x1,y0,y1) 2k+1:(z0,z1,w0,w1)
__device__ float4   g_col[NB * NPTS];          // (-2x, -2y, -2z, ||x||^2)
__device__ unsigned g_rowmin[NB * NPTS];
__device__ unsigned g_colmin[NB * NPTS];

__device__ __forceinline__ unsigned flipf(float f) {
    unsigned b = __float_as_uint(f);
    return b ^ (0x80000000u | (unsigned)((int)b >> 31));
}
__device__ __forceinline__ float unflipf(unsigned u) {
    unsigned b = (u & 0x80000000u) ? (u ^ 0x80000000u) : ~u;
    return __uint_as_float(b);
}
__device__ __forceinline__ unsigned long long pack2(float a, float b) {
    unsigned long long r;
    asm("mov.b64 %0, {%1, %2};" : "=l"(r) : "f"(a), "f"(b));
    return r;
}
__device__ __forceinline__ float fmin3(float a, float b, float c) {
    float r;
    asm("min.f32 %0, %1, %2, %3;" : "=f"(r) : "f"(a), "f"(b), "f"(c));
    return r;
}

// ---------------------------------------------------------------------------
__global__ void pack_kernel(const float* __restrict__ x,
                            const float* __restrict__ y,
                            float* __restrict__ out) {
    int k = blockIdx.x * blockDim.x + threadIdx.x;
    if (k == 0) out[0] = 0.0f;
    if (k >= NB * NPTS / 2) return;

    int i0 = 2 * k, i1 = 2 * k + 1;
    {
        const float* p0 = y + (size_t)i0 * 3;
        const float* p1 = y + (size_t)i1 * 3;
        float x0 = p0[0], y0 = p0[1], z0 = p0[2];
        float x1 = p1[0], y1 = p1[1], z1 = p1[2];
        g_rowpair[2 * k + 0] = make_float4(x0, x1, y0, y1);
        g_rowpair[2 * k + 1] = make_float4(z0, z1,
                                           x0 * x0 + y0 * y0 + z0 * z0,
                                           x1 * x1 + y1 * y1 + z1 * z1);
    }
    {
        const float* p0 = x + (size_t)i0 * 3;
        const float* p1 = x + (size_t)i1 * 3;
        float a = p0[0], b = p0[1], c = p0[2];
        g_col[i0] = make_float4(-2.f * a, -2.f * b, -2.f * c, a * a + b * b + c * c);
        float u = p1[0], v = p1[1], w = p1[2];
        g_col[i1] = make_float4(-2.f * u, -2.f * v, -2.f * w, u * u + v * v + w * w);
    }
    g_rowmin[i0] = 0xFFFFFFFFu; g_rowmin[i1] = 0xFFFFFFFFu;
    g_colmin[i0] = 0xFFFFFFFFu; g_colmin[i1] = 0xFFFFFFFFu;
}

// ---------------------------------------------------------------------------
// Fused pass: grid (CCHUNKS, ROWSPLIT, NB) = (4, 32, 16) = 2048 blocks.
// Hot loop (per 2 rows, 512 pairs): 32 FFMA2/FADD2 + 8 mov + 16 min3/min — NO
// shuffles, NO atomics. Cross-lane rowmin done once per 16 rows via padded
// smem transpose (conflict-free) + 16-lane predicated RED.
// ---------------------------------------------------------------------------
__global__ __launch_bounds__(THREADS, 4)
void chamfer_fused_kernel() {
    __shared__ float4 rowtile[RPAIRS * 2];             // 2 KB
    __shared__ float  tbuf[WARPS][16 * 33];            // 4 * 2112 B, padded stride 33

    const int b  = blockIdx.z;
    const int rs = blockIdx.y;
    const int cc = blockIdx.x;

    const int row0 = rs * ROWS_PER_BLOCK;
    const int j0   = cc * CANDS_PER_BLOCK + threadIdx.x * C;

    const float4* __restrict__ RPbase = g_rowpair + (size_t)b * NPTS + row0;
    const float4* __restrict__ Cd     = g_col     + (size_t)b * NPTS + j0;

    unsigned long long cxd[C], cyd[C], czd[C], cwd[C];
    float cm[C];
#pragma unroll
    for (int c = 0; c < C; c++) {
        float4 f = Cd[c];
        cxd[c] = pack2(f.x, f.x);
        cyd[c] = pack2(f.y, f.y);
        czd[c] = pack2(f.z, f.z);
        cwd[c] = pack2(f.w, f.w);
        cm[c]  = 3.4e38f;
    }

    for (int i = threadIdx.x; i < RPAIRS * 2; i += THREADS)
        rowtile[i] = RPbase[i];
    __syncthreads();

    const int lane = threadIdx.x & 31;
    const int wid  = threadIdx.x >> 5;
    float* tb = tbuf[wid];
    const ulonglong2* tp = (const ulonglong2*)rowtile;

    for (int g = 0; g < GROUPS; g++) {
        float r0s[TPG], r1s[TPG];

#pragma unroll
        for (int t = 0; t < TPG; t++) {
            const int rp = g * TPG + t;
            ulonglong2 e0 = tp[2 * rp + 0];   // .x = xpair, .y = ypair
            ulonglong2 e1 = tp[2 * rp + 1];   // .x = zpair, .y = wpair (y2)

            float v0s[C], v1s[C];
#pragma unroll
            for (int c = 0; c < C; c++) {
                unsigned long long t64;
                asm("fma.rn.f32x2 %0, %1, %2, %3;" : "=l"(t64) : "l"(e1.x), "l"(czd[c]), "l"(cwd[c]));
                asm("fma.rn.f32x2 %0, %1, %2, %0;" : "+l"(t64) : "l"(e0.y), "l"(cyd[c]));
                asm("fma.rn.f32x2 %0, %1, %2, %0;" : "+l"(t64) : "l"(e0.x), "l"(cxd[c]));
                asm("add.rn.f32x2 %0, %0, %1;"     : "+l"(t64) : "l"(e1.y));
                float v0, v1;
                asm("mov.b64 {%0, %1}, %2;" : "=f"(v0), "=f"(v1) : "l"(t64));
                v0s[c] = v0; v1s[c] = v1;
                cm[c] = fmin3(cm[c], v0, v1);
            }
            // Per-row trees over 8 candidates (4 ops each)
            r0s[t] = fmin3(fmin3(v0s[0], v0s[1], v0s[2]),
                           fmin3(v0s[3], v0s[4], v0s[5]),
                           fminf(v0s[6], v0s[7]));
            r1s[t] = fmin3(fmin3(v1s[0], v1s[1], v1s[2]),
                           fmin3(v1s[3], v1s[4], v1s[5]),
                           fminf(v1s[6], v1s[7]));
        }

        // ---- Transpose-reduce 16 rows x 32 lanes (per warp) ----
#pragma unroll
        for (int t = 0; t < TPG; t++) {
            tb[(2 * t + 0) * 33 + lane] = r0s[t];
            tb[(2 * t + 1) * 33 + lane] = r1s[t];
        }
        __syncwarp();

        {
            const int k    = lane >> 1;          // row within group (0..15)
            const int half = lane & 1;           // which 16 lanes to reduce
            const float* src = tb + k * 33 + half * 16;
            float a0 = src[0],  a1 = src[1],  a2 = src[2],  a3 = src[3];
            float a4 = src[4],  a5 = src[5],  a6 = src[6],  a7 = src[7];
            float a8 = src[8],  a9 = src[9],  aA = src[10], aB = src[11];
            float aC = src[12], aD = src[13], aE = src[14], aF = src[15];
            float m = fmin3(fmin3(fmin3(a0, a1, a2),  fmin3(a3, a4, a5),  fmin3(a6, a7, a8)),
                            fmin3(fmin3(a9, aA, aB),  fmin3(aC, aD, aE),  aF),
                            3.4e38f);
            m = fminf(m, __shfl_xor_sync(0xFFFFFFFFu, m, 1));
            if (half == 0)
                atomicMin(&g_rowmin[b * NPTS + row0 + g * 16 + k], flipf(m));
        }
        __syncwarp();
    }

    // Flush colmin partials
#pragma unroll
    for (int c = 0; c < C; c++)
        atomicMin(&g_colmin[b * NPTS + j0 + c], flipf(cm[c]));
}

// ---------------------------------------------------------------------------
__global__ void finalize_kernel(float* __restrict__ out) {
    int idx = blockIdx.x * blockDim.x + threadIdx.x;

    float local = 0.0f;
    if (idx < NB * NPTS) {
        float vr = unflipf(g_rowmin[idx]);
        float vc = unflipf(g_colmin[idx]);
        local  = sqrtf(EPS + fmaxf(vr, 0.0f));
        local += sqrtf(EPS + fmaxf(vc, 0.0f));
    }

#pragma unroll
    for (int o = 16; o > 0; o >>= 1)
        local += __shfl_down_sync(0xFFFFFFFFu, local, o);

    __shared__ float warp_sums[8];
    int lane = threadIdx.x & 31;
    int wid  = threadIdx.x >> 5;
    if (lane == 0) warp_sums[wid] = local;
    __syncthreads();
    if (wid == 0) {
        float sv = (lane < (int)(blockDim.x >> 5)) ? warp_sums[lane] : 0.0f;
#pragma unroll
        for (int o = 4; o > 0; o >>= 1)
            sv += __shfl_down_sync(0xFFFFFFFFu, sv, o);
        if (lane == 0) atomicAdd(out, sv * (1.0f / (float)TOTAL_Q));
    }
}

extern "C" void kernel_launch(void* const* d_in, const int* in_sizes, int n_in,
                              void* d_out, int out_size) {
    const float* x = (const float*)d_in[0];
    const float* y = (const float*)d_in[1];
    float* out = (float*)d_out;

    pack_kernel<<<(NB * NPTS / 2 + 255) / 256, 256>>>(x, y, out);

    dim3 grid(CCHUNKS, ROWSPLIT, NB);   // (4, 32, 16) = 2048 blocks
    chamfer_fused_kernel<<<grid, THREADS>>>();

    finalize_kernel<<<(NB * NPTS + 255) / 256, 256>>>(out);
}